// round 15
// baseline (speedup 1.0000x reference)
#include <cuda_runtime.h>
#include <math.h>

#define NB     64
#define DIM    8
#define NPTS   2097152
#define BETA_F 1e-6f
#define LOG_BETA (-13.815511f)
#define LN2_F  0.69314718f
#define EIGHT_LN20 23.9658588f   // 8 * ln(20)

// Geometric-mesh inversion: tg = |x|*(R^32-1)/10 + 1, j = floor(log2(tg)/log2(1.2))
#define GEO_C1   34.0821892f     // (1.2^32 - 1) / 10
#define GEO_INVL 3.80178402f     // 1 / log2(1.2)

#define TPB    256
#define GRID   1024              // one wave at 7 blocks/SM; 4 clean iterations
#define ITERS  4
#define F4_PER_ITER (GRID * TPB * 4)   // 1048576 float4s per iteration

// Scaled coefficients: yy(u) = Q0 + u*(Q1 + u*Q2) in output space,
// DD(u) = Q1 + 2u*Q2 = 20*dld (log corrected by -8*ln20), u = x/20.
// Slot map: pos bin j -> j ; neg bin j -> 32+((j+16)&31)
__device__ float g_q[3 * DIM * NB];
__device__ int   g_flag;

union SmemU {
    float q[3 * DIM * NB];       // 6 KB staged table
    struct {
        float mesh[NB + 1];
        float elmt[NB];
        float pdf[DIM][NB + 1];
    } su;
};

__global__ void __launch_bounds__(TPB, 7)
cdf_fused_kernel(const float*  __restrict__ x,
                 const float*  __restrict__ logdet_in,
                 const float*  __restrict__ p,
                 float*        __restrict__ y_out,
                 float*        __restrict__ ld_out)
{
    __shared__ SmemU sm;

    const int t = threadIdx.x;

    if (blockIdx.x == 0) {
        // ---- table build, pure f32, once per launch ----
        if (t <= NB) {
            int e = t - 32;
            int a = e < 0 ? -e : e;
            float r1 = 1.2f, r2 = r1 * r1, r4 = r2 * r2, r8 = r4 * r4,
                  r16 = r8 * r8, r32 = r16 * r16;
            float pw = 1.0f;
            if (a & 1)  pw *= r1;
            if (a & 2)  pw *= r2;
            if (a & 4)  pw *= r4;
            if (a & 8)  pw *= r8;
            if (a & 16) pw *= r16;
            float xr = (10.0f / (r32 - 1.0f)) * (pw - 1.0f);
            if (e < 0) xr = -xr;
            xr = fmaf(xr, 0.05f, 0.5f);
            float mv = xr;
            if (t == 0)  mv = 0.0f;
            if (t == NB) mv = 1.0f;
            sm.su.mesh[t] = mv;
        }
        __syncthreads();
        if (t < NB) sm.su.elmt[t] = sm.su.mesh[t + 1] - sm.su.mesh[t];
        __syncthreads();

        const int d = t >> 5;
        const int l = t & 31;

        float ep_a = expf(p[l * DIM + d]);
        float ep_b = (l < 31) ? expf(p[(l + 32) * DIM + d]) : 0.0f;

        float wa = 0.5f * (sm.su.elmt[l] + sm.su.elmt[l + 1]);
        float wb = (l < 31) ? 0.5f * (sm.su.elmt[l + 32] + sm.su.elmt[l + 33]) : 0.0f;
        float sum = ep_a * wa + ep_b * wb;
#pragma unroll
        for (int o = 16; o; o >>= 1) sum += __shfl_xor_sync(0xFFFFFFFFu, sum, o);
        float scale = (1.0f - (sm.su.elmt[0] + sm.su.elmt[NB - 1]) * BETA_F * 0.5f) / sum;

        if (l == 0) { sm.su.pdf[d][0] = BETA_F; sm.su.pdf[d][NB] = BETA_F; }
        sm.su.pdf[d][l + 1] = scale * ep_a;
        if (l < 31) sm.su.pdf[d][l + 33] = scale * ep_b;
        __syncwarp();

        float ca = 0.5f * (sm.su.pdf[d][l]      + sm.su.pdf[d][l + 1])  * sm.su.elmt[l];
        float cb = 0.5f * (sm.su.pdf[d][l + 32] + sm.su.pdf[d][l + 33]) * sm.su.elmt[l + 32];

        float A = ca, B = cb;
#pragma unroll
        for (int o = 1; o < 32; o <<= 1) {
            float va = __shfl_up_sync(0xFFFFFFFFu, A, o);
            float vb = __shfl_up_sync(0xFFFFFFFFu, B, o);
            if (l >= o) { A += va; B += vb; }
        }
        float A31 = __shfl_sync(0xFFFFFFFFu, A, 31);
        float Fa = A - ca;
        float Fb = A31 + B - cb;

#pragma unroll
        for (int half = 0; half < 2; half++) {
            int k = l + half * 32;
            float v1    = sm.su.pdf[d][k];
            float v2    = sm.su.pdf[d][k + 1];
            float h     = sm.su.elmt[k];
            float slope = (v2 - v1) / h;
            float mks   = sm.su.mesh[k] - 0.5f;
            float F     = half ? Fb : Fa;
            float q1    = v1 - mks * slope;
            float q0    = F - mks * v1 + 0.5f * mks * mks * slope;
            int s = (k >= 32) ? (k - 32) : (32 + ((47 - k) & 31));
            int ti = d * NB + s;
            g_q[ti]        = fmaf(q0, 20.0f, -10.0f);  // Q0
            g_q[ti + 512]  = 20.0f * q1;               // Q1
            g_q[ti + 1024] = 10.0f * slope;            // Q2
        }

        __threadfence();
        __syncthreads();
        if (t == 0) atomicExch(&g_flag, 1);
    } else {
        if (t == 0) {
            volatile int* f = &g_flag;
            while (*f != 1) { __nanosleep(64); }
            __threadfence();
        }
        __syncthreads();
    }

    // ---- stage table to shared: once per resident block ----
    if (t < 128) {
        ((float4*)sm.q)[t]       = ((const float4*)g_q)[t];
        ((float4*)sm.q)[t + 128] = ((const float4*)g_q)[t + 128];
        ((float4*)sm.q)[t + 256] = ((const float4*)g_q)[t + 256];
    }
    __syncthreads();

    const float* s_q0 = sm.q;
    const float* s_q1 = sm.q + 512;
    const float* s_q2 = sm.q + 1024;

    const int lane = t & 31;
    const int half = lane & 1;           // 0: dims 0-3, 1: dims 4-7
    const int off  = half << 8;          // d*64 base for this half (4*64=256)
    const int c    = lane >> 1;          // pair index 0..15
    const int gw   = blockIdx.x * (TPB / 32) + (t >> 5);   // global warp id

    const float4* xf4 = (const float4*)x;
    float4*       yf4 = (float4*)y_out;

#pragma unroll 1
    for (int it = 0; it < ITERS; it++) {
        const int Fb4 = it * F4_PER_ITER + gw * 128;    // warp's float4 base
        const int P   = Fb4 >> 1;                       // warp's point base

        // Lane-contiguous float4 loads: 4 lines per LDG.128 (HW minimum)
        float4 v0 = xf4[Fb4 + lane];
        float4 v1 = xf4[Fb4 + lane + 32];
        float4 v2 = xf4[Fb4 + lane + 64];
        float4 v3 = xf4[Fb4 + lane + 96];

        float ldin0 = 0.f, ldin1 = 0.f, ldin2 = 0.f, ldin3 = 0.f;
        if (half == 0) {
            ldin0 = logdet_in[P + c];
            ldin1 = logdet_in[P + 16 + c];
            ldin2 = logdet_in[P + 32 + c];
            ldin3 = logdet_in[P + 48 + c];
        }

#pragma unroll
        for (int m = 0; m < 4; m++) {
            float4 v = (m == 0) ? v0 : (m == 1) ? v1 : (m == 2) ? v2 : v3;
            float xr4[4] = {v.x, v.y, v.z, v.w};
            float yv4[4];
            float lsum = 0.0f;
            float prod = 1.0f;

#pragma unroll
            for (int r = 0; r < 4; r++) {
                float xi = xr4[r];
                float u  = xi * 0.05f;

                float tg = fmaf(fabsf(xi), GEO_C1, 1.0f);
                int   j  = (int)(__log2f(tg) * GEO_INVL);
                j = min(j, 31);
                int s = (xi < 0.0f) ? (32 + ((j + 16) & 31)) : j;

                int   ti = off + r * 64 + s;
                float Q0 = s_q0[ti], Q1 = s_q1[ti], Q2 = s_q2[ti];

                float inner = fmaf(u, Q2, Q1);
                float yy    = fmaf(u, inner, Q0);
                float DD    = fmaf(u, Q2, inner);    // 20*dld

                bool ncov = (xi < -10.0f) || (xi >= 10.0f);
                if (ncov || fabsf(yy) > 10.0f) {     // never taken for N(0,1)
                    if (ncov) { yy = xi; DD = 20.0f; }
                    if (yy > 10.0f)  { lsum += LOG_BETA; yy = fmaf(BETA_F, yy - 10.0f,  10.0f); }
                    if (yy < -10.0f) { lsum += LOG_BETA; yy = fmaf(BETA_F, yy + 10.0f, -10.0f); }
                }

                prod *= DD;
                yv4[r] = yy;
            }

            // Pair exchange: combine the two halves of this point
            float oprod = __shfl_xor_sync(0xFFFFFFFFu, prod, 1);
            float olsum = __shfl_xor_sync(0xFFFFFFFFu, lsum, 1);

            yf4[Fb4 + lane + 32 * m] = make_float4(yv4[0], yv4[1], yv4[2], yv4[3]);

            if (half == 0) {
                float ldin = (m == 0) ? ldin0 : (m == 1) ? ldin1 : (m == 2) ? ldin2 : ldin3;
                float tot = lsum + olsum +
                            fmaf(__log2f(prod * oprod), LN2_F, -EIGHT_LN20);
                ld_out[P + 16 * m + c] = ldin + tot;
            }
        }
    }
}

extern "C" void kernel_launch(void* const* d_in, const int* in_sizes, int n_in,
                              void* d_out, int out_size)
{
    const float* x      = (const float*)d_in[0];
    const float* logdet = (const float*)d_in[1];
    const float* p      = (const float*)d_in[2];
    float* out    = (float*)d_out;
    float* y_out  = out;                        // [N*8]
    float* ld_out = out + (size_t)NPTS * DIM;   // [N]

    cdf_fused_kernel<<<GRID, TPB>>>(x, logdet, p, y_out, ld_out);
}

// round 16
// speedup vs baseline: 1.5262x; 1.5262x over previous
#include <cuda_runtime.h>
#include <math.h>

#define NB     64
#define DIM    8
#define NPTS   2097152
#define BETA_F 1e-6f
#define LOG_BETA (-13.815511f)
#define LN2_F  0.69314718f
#define EIGHT_LN20 23.9658588f   // 8 * ln(20)

// Geometric-mesh inversion: tg = |x|*(R^32-1)/10 + 1, j = floor(log2(tg)/log2(1.2))
#define GEO_C1   34.0821892f     // (1.2^32 - 1) / 10
#define GEO_INVL 3.80178402f     // 1 / log2(1.2)

#define TPB    256
#define GRID   1184              // 148 SMs x 8 blocks: one persistent wave
#define STRIDE (GRID * TPB)

// Scaled coefficients: yy(u) = Q0 + u*(Q1 + u*Q2) in output space,
// DD(u) = Q1 + 2u*Q2 = 20*dld (log corrected by -8*ln20), u = x/20.
// Slot map (probability-aware banks): pos bin j -> j ; neg bin j -> 32+((j+16)&31)
__device__ float g_q[3 * DIM * NB];
__device__ int   g_flag;

union SmemU {
    float q[3 * DIM * NB];       // 6 KB staged table
    struct {
        float mesh[NB + 1];
        float elmt[NB];
        float pdf[DIM][NB + 1];
    } su;
};

__global__ void __launch_bounds__(TPB, 8)
cdf_fused_kernel(const float*  __restrict__ x,
                 const float*  __restrict__ logdet_in,
                 const float*  __restrict__ p,
                 float*        __restrict__ y_out,
                 float*        __restrict__ ld_out)
{
    __shared__ SmemU sm;

    const int t = threadIdx.x;

    if (blockIdx.x == 0) {
        // ---- table build, pure f32, once per launch ----
        if (t <= NB) {
            int e = t - 32;
            int a = e < 0 ? -e : e;
            float r1 = 1.2f, r2 = r1 * r1, r4 = r2 * r2, r8 = r4 * r4,
                  r16 = r8 * r8, r32 = r16 * r16;
            float pw = 1.0f;
            if (a & 1)  pw *= r1;
            if (a & 2)  pw *= r2;
            if (a & 4)  pw *= r4;
            if (a & 8)  pw *= r8;
            if (a & 16) pw *= r16;
            float xr = (10.0f / (r32 - 1.0f)) * (pw - 1.0f);
            if (e < 0) xr = -xr;
            xr = fmaf(xr, 0.05f, 0.5f);
            float mv = xr;
            if (t == 0)  mv = 0.0f;
            if (t == NB) mv = 1.0f;
            sm.su.mesh[t] = mv;
        }
        __syncthreads();
        if (t < NB) sm.su.elmt[t] = sm.su.mesh[t + 1] - sm.su.mesh[t];
        __syncthreads();

        const int d = t >> 5;
        const int l = t & 31;

        float ep_a = expf(p[l * DIM + d]);
        float ep_b = (l < 31) ? expf(p[(l + 32) * DIM + d]) : 0.0f;

        float wa = 0.5f * (sm.su.elmt[l] + sm.su.elmt[l + 1]);
        float wb = (l < 31) ? 0.5f * (sm.su.elmt[l + 32] + sm.su.elmt[l + 33]) : 0.0f;
        float sum = ep_a * wa + ep_b * wb;
#pragma unroll
        for (int o = 16; o; o >>= 1) sum += __shfl_xor_sync(0xFFFFFFFFu, sum, o);
        float scale = (1.0f - (sm.su.elmt[0] + sm.su.elmt[NB - 1]) * BETA_F * 0.5f) / sum;

        if (l == 0) { sm.su.pdf[d][0] = BETA_F; sm.su.pdf[d][NB] = BETA_F; }
        sm.su.pdf[d][l + 1] = scale * ep_a;
        if (l < 31) sm.su.pdf[d][l + 33] = scale * ep_b;
        __syncwarp();

        float ca = 0.5f * (sm.su.pdf[d][l]      + sm.su.pdf[d][l + 1])  * sm.su.elmt[l];
        float cb = 0.5f * (sm.su.pdf[d][l + 32] + sm.su.pdf[d][l + 33]) * sm.su.elmt[l + 32];

        float A = ca, B = cb;
#pragma unroll
        for (int o = 1; o < 32; o <<= 1) {
            float va = __shfl_up_sync(0xFFFFFFFFu, A, o);
            float vb = __shfl_up_sync(0xFFFFFFFFu, B, o);
            if (l >= o) { A += va; B += vb; }
        }
        float A31 = __shfl_sync(0xFFFFFFFFu, A, 31);
        float Fa = A - ca;
        float Fb = A31 + B - cb;

#pragma unroll
        for (int half = 0; half < 2; half++) {
            int k = l + half * 32;
            float v1    = sm.su.pdf[d][k];
            float v2    = sm.su.pdf[d][k + 1];
            float h     = sm.su.elmt[k];
            float slope = (v2 - v1) / h;
            float mks   = sm.su.mesh[k] - 0.5f;
            float F     = half ? Fb : Fa;
            float q1    = v1 - mks * slope;
            float q0    = F - mks * v1 + 0.5f * mks * mks * slope;
            int s = (k >= 32) ? (k - 32) : (32 + ((47 - k) & 31));
            int ti = d * NB + s;
            g_q[ti]        = fmaf(q0, 20.0f, -10.0f);  // Q0
            g_q[ti + 512]  = 20.0f * q1;               // Q1
            g_q[ti + 1024] = 10.0f * slope;            // Q2
        }

        __threadfence();
        __syncthreads();
        if (t == 0) atomicExch(&g_flag, 1);
    } else {
        if (t == 0) {
            volatile int* f = &g_flag;
            while (*f != 1) { __nanosleep(64); }
            __threadfence();
        }
        __syncthreads();
    }

    // ---- stage table to shared: once per resident block ----
    if (t < 128) {
        ((float4*)sm.q)[t]       = ((const float4*)g_q)[t];
        ((float4*)sm.q)[t + 128] = ((const float4*)g_q)[t + 128];
        ((float4*)sm.q)[t + 256] = ((const float4*)g_q)[t + 256];
    }
    __syncthreads();

    const float* s_q0 = sm.q;
    const float* s_q1 = sm.q + 512;
    const float* s_q2 = sm.q + 1024;

    // ---- persistent grid-stride loop ----
#pragma unroll 1
    for (int i = blockIdx.x * TPB + t; i < NPTS; i += STRIDE) {
        const float4* xv = (const float4*)(x + (size_t)i * DIM);
        float4 a4 = xv[0], b4 = xv[1];
        float ld_in = logdet_in[i];

        // Prefetch next iteration's x into L2 (zero register cost).
        {
            int nxt = i + STRIDE;
            if (nxt < NPTS) {
                const float* np = x + (size_t)nxt * DIM;
                asm volatile("prefetch.global.L2 [%0];" :: "l"(np));
            }
        }

        float xr[DIM] = {a4.x, a4.y, a4.z, a4.w, b4.x, b4.y, b4.z, b4.w};
        float yv[DIM];
        float prod0 = 1.0f, prod1 = 1.0f;
        float amax = 0.0f, ymax = 0.0f;

        // ---- fast pass: no per-dim branches; track trigger maxima ----
#pragma unroll
        for (int d = 0; d < DIM; d++) {
            float xi = xr[d];
            float u  = xi * 0.05f;
            float ax = fabsf(xi);

            float tg = fmaf(ax, GEO_C1, 1.0f);
            int   j  = (int)(__log2f(tg) * GEO_INVL);
            j = min(j, 31);
            int s = (xi < 0.0f) ? (32 + ((j + 16) & 31)) : j;

            int   ti = d * NB + s;
            float Q0 = s_q0[ti], Q1 = s_q1[ti], Q2 = s_q2[ti];

            float inner = fmaf(u, Q2, Q1);
            float yy    = fmaf(u, inner, Q0);
            float DD    = fmaf(u, Q2, inner);    // 20*dld

            amax = fmaxf(amax, ax);
            ymax = fmaxf(ymax, fabsf(yy));
            if (d < 4) prod0 *= DD; else prod1 *= DD;
            yv[d] = yy;
        }

        float lsum = 0.0f;

        // ---- rare exact path: out-of-cover or boundary clamp ----
        // Never taken for N(0,1) inputs; full reference semantics inside.
        if (amax >= 10.0f || ymax > 10.0f) {
            prod0 = 1.0f; prod1 = 1.0f; lsum = 0.0f;
#pragma unroll
            for (int d = 0; d < DIM; d++) {
                float xi = xr[d];
                float u  = xi * 0.05f;

                float tg = fmaf(fabsf(xi), GEO_C1, 1.0f);
                int   j  = (int)(__log2f(tg) * GEO_INVL);
                j = min(j, 31);
                int s = (xi < 0.0f) ? (32 + ((j + 16) & 31)) : j;

                int   ti = d * NB + s;
                float Q0 = s_q0[ti], Q1 = s_q1[ti], Q2 = s_q2[ti];

                float inner = fmaf(u, Q2, Q1);
                float yy    = fmaf(u, inner, Q0);
                float DD    = fmaf(u, Q2, inner);

                bool ncov = (xi < -10.0f) || (xi >= 10.0f);
                if (ncov) { yy = xi; DD = 20.0f; }   // dld=1 -> DD=20
                if (yy > 10.0f)  { lsum += LOG_BETA; yy = fmaf(BETA_F, yy - 10.0f,  10.0f); }
                if (yy < -10.0f) { lsum += LOG_BETA; yy = fmaf(BETA_F, yy + 10.0f, -10.0f); }

                if (d < 4) prod0 *= DD; else prod1 *= DD;
                yv[d] = yy;
            }
        }

        lsum = fmaf(__log2f(prod0) + __log2f(prod1), LN2_F, lsum) - EIGHT_LN20;

        float4* yo = (float4*)(y_out + (size_t)i * DIM);
        yo[0] = make_float4(yv[0], yv[1], yv[2], yv[3]);
        yo[1] = make_float4(yv[4], yv[5], yv[6], yv[7]);
        ld_out[i] = ld_in + lsum;
    }
}

extern "C" void kernel_launch(void* const* d_in, const int* in_sizes, int n_in,
                              void* d_out, int out_size)
{
    const float* x      = (const float*)d_in[0];
    const float* logdet = (const float*)d_in[1];
    const float* p      = (const float*)d_in[2];
    float* out    = (float*)d_out;
    float* y_out  = out;                        // [N*8]
    float* ld_out = out + (size_t)NPTS * DIM;   // [N]

    cdf_fused_kernel<<<GRID, TPB>>>(x, logdet, p, y_out, ld_out);
}

// round 17
// speedup vs baseline: 1.6334x; 1.0703x over previous
#include <cuda_runtime.h>
#include <math.h>

#define NB     64
#define DIM    8
#define NPTS   2097152
#define BETA_F 1e-6f
#define LOG_BETA (-13.815511f)
#define LN2_F  0.69314718f
#define EIGHT_LN20 23.9658588f   // 8 * ln(20)

// Geometric-mesh inversion: tg = |x|*(R^32-1)/10 + 1, j = floor(log2(tg)/log2(1.2))
#define GEO_C1   34.0821892f     // (1.2^32 - 1) / 10
#define GEO_INVL 3.80178402f     // 1 / log2(1.2)

#define TPB    256
#define GRID   1184              // 148 SMs x 8 blocks: one persistent wave
#define STRIDE (GRID * TPB)

// Scaled coefficients: yy(u) = Q0 + u*(Q1 + u*Q2) in output space,
// DD(u) = Q1 + 2u*Q2 = 20*dld (log corrected by -8*ln20), u = x/20.
// Slot map (probability-aware banks): pos bin j -> j ; neg bin j -> 32+((j+16)&31)
__device__ float g_q[3 * DIM * NB];
__device__ int   g_flag;

union SmemU {
    float q[3 * DIM * NB];       // 6 KB staged table
    struct {
        float mesh[NB + 1];
        float elmt[NB];
        float pdf[DIM][NB + 1];
    } su;
};

// 256-bit global load/store (Blackwell LDG.E.256 / STG.E.256), 32B-aligned.
__device__ __forceinline__ void ldg256(const float* p, float* v) {
    asm volatile("ld.global.v8.f32 {%0,%1,%2,%3,%4,%5,%6,%7}, [%8];"
                 : "=f"(v[0]), "=f"(v[1]), "=f"(v[2]), "=f"(v[3]),
                   "=f"(v[4]), "=f"(v[5]), "=f"(v[6]), "=f"(v[7])
                 : "l"(p));
}
__device__ __forceinline__ void stg256(float* p, const float* v) {
    asm volatile("st.global.v8.f32 [%0], {%1,%2,%3,%4,%5,%6,%7,%8};"
                 :: "l"(p),
                    "f"(v[0]), "f"(v[1]), "f"(v[2]), "f"(v[3]),
                    "f"(v[4]), "f"(v[5]), "f"(v[6]), "f"(v[7])
                 : "memory");
}

__global__ void __launch_bounds__(TPB, 8)
cdf_fused_kernel(const float*  __restrict__ x,
                 const float*  __restrict__ logdet_in,
                 const float*  __restrict__ p,
                 float*        __restrict__ y_out,
                 float*        __restrict__ ld_out)
{
    __shared__ SmemU sm;

    const int t = threadIdx.x;

    if (blockIdx.x == 0) {
        // ---- table build, pure f32, once per launch ----
        if (t <= NB) {
            int e = t - 32;
            int a = e < 0 ? -e : e;
            float r1 = 1.2f, r2 = r1 * r1, r4 = r2 * r2, r8 = r4 * r4,
                  r16 = r8 * r8, r32 = r16 * r16;
            float pw = 1.0f;
            if (a & 1)  pw *= r1;
            if (a & 2)  pw *= r2;
            if (a & 4)  pw *= r4;
            if (a & 8)  pw *= r8;
            if (a & 16) pw *= r16;
            float xr = (10.0f / (r32 - 1.0f)) * (pw - 1.0f);
            if (e < 0) xr = -xr;
            xr = fmaf(xr, 0.05f, 0.5f);
            float mv = xr;
            if (t == 0)  mv = 0.0f;
            if (t == NB) mv = 1.0f;
            sm.su.mesh[t] = mv;
        }
        __syncthreads();
        if (t < NB) sm.su.elmt[t] = sm.su.mesh[t + 1] - sm.su.mesh[t];
        __syncthreads();

        const int d = t >> 5;
        const int l = t & 31;

        float ep_a = expf(p[l * DIM + d]);
        float ep_b = (l < 31) ? expf(p[(l + 32) * DIM + d]) : 0.0f;

        float wa = 0.5f * (sm.su.elmt[l] + sm.su.elmt[l + 1]);
        float wb = (l < 31) ? 0.5f * (sm.su.elmt[l + 32] + sm.su.elmt[l + 33]) : 0.0f;
        float sum = ep_a * wa + ep_b * wb;
#pragma unroll
        for (int o = 16; o; o >>= 1) sum += __shfl_xor_sync(0xFFFFFFFFu, sum, o);
        float scale = (1.0f - (sm.su.elmt[0] + sm.su.elmt[NB - 1]) * BETA_F * 0.5f) / sum;

        if (l == 0) { sm.su.pdf[d][0] = BETA_F; sm.su.pdf[d][NB] = BETA_F; }
        sm.su.pdf[d][l + 1] = scale * ep_a;
        if (l < 31) sm.su.pdf[d][l + 33] = scale * ep_b;
        __syncwarp();

        float ca = 0.5f * (sm.su.pdf[d][l]      + sm.su.pdf[d][l + 1])  * sm.su.elmt[l];
        float cb = 0.5f * (sm.su.pdf[d][l + 32] + sm.su.pdf[d][l + 33]) * sm.su.elmt[l + 32];

        float A = ca, B = cb;
#pragma unroll
        for (int o = 1; o < 32; o <<= 1) {
            float va = __shfl_up_sync(0xFFFFFFFFu, A, o);
            float vb = __shfl_up_sync(0xFFFFFFFFu, B, o);
            if (l >= o) { A += va; B += vb; }
        }
        float A31 = __shfl_sync(0xFFFFFFFFu, A, 31);
        float Fa = A - ca;
        float Fb = A31 + B - cb;

#pragma unroll
        for (int half = 0; half < 2; half++) {
            int k = l + half * 32;
            float v1    = sm.su.pdf[d][k];
            float v2    = sm.su.pdf[d][k + 1];
            float h     = sm.su.elmt[k];
            float slope = (v2 - v1) / h;
            float mks   = sm.su.mesh[k] - 0.5f;
            float F     = half ? Fb : Fa;
            float q1    = v1 - mks * slope;
            float q0    = F - mks * v1 + 0.5f * mks * mks * slope;
            int s = (k >= 32) ? (k - 32) : (32 + ((47 - k) & 31));
            int ti = d * NB + s;
            g_q[ti]        = fmaf(q0, 20.0f, -10.0f);  // Q0
            g_q[ti + 512]  = 20.0f * q1;               // Q1
            g_q[ti + 1024] = 10.0f * slope;            // Q2
        }

        __threadfence();
        __syncthreads();
        if (t == 0) atomicExch(&g_flag, 1);
    } else {
        if (t == 0) {
            volatile int* f = &g_flag;
            while (*f != 1) { __nanosleep(64); }
            __threadfence();
        }
        __syncthreads();
    }

    // ---- stage table to shared: once per resident block ----
    if (t < 128) {
        ((float4*)sm.q)[t]       = ((const float4*)g_q)[t];
        ((float4*)sm.q)[t + 128] = ((const float4*)g_q)[t + 128];
        ((float4*)sm.q)[t + 256] = ((const float4*)g_q)[t + 256];
    }
    __syncthreads();

    const float* s_q0 = sm.q;
    const float* s_q1 = sm.q + 512;
    const float* s_q2 = sm.q + 1024;

    // ---- persistent grid-stride loop ----
#pragma unroll 1
    for (int i = blockIdx.x * TPB + t; i < NPTS; i += STRIDE) {
        float xr[DIM];
        ldg256(x + (size_t)i * DIM, xr);        // one LDG.E.256 per point
        float ld_in = logdet_in[i];

        float yv[DIM];
        float lsum = 0.0f;
        float prod0 = 1.0f, prod1 = 1.0f;

#pragma unroll
        for (int d = 0; d < DIM; d++) {
            float xi = xr[d];
            float u  = xi * 0.05f;

            float tg = fmaf(fabsf(xi), GEO_C1, 1.0f);
            int   j  = (int)(__log2f(tg) * GEO_INVL);
            j = min(j, 31);
            int s = (xi < 0.0f) ? (32 + ((j + 16) & 31)) : j;

            int   ti = d * NB + s;
            float Q0 = s_q0[ti], Q1 = s_q1[ti], Q2 = s_q2[ti];

            float inner = fmaf(u, Q2, Q1);
            float yy    = fmaf(u, inner, Q0);
            float DD    = fmaf(u, Q2, inner);    // 20*dld

            // Rare path: out-of-cover or boundary clamp; never taken for N(0,1).
            bool ncov = (xi < -10.0f) || (xi >= 10.0f);
            if (ncov || fabsf(yy) > 10.0f) {
                if (ncov) { yy = xi; DD = 20.0f; }   // dld=1 -> DD=20
                if (yy > 10.0f)  { lsum += LOG_BETA; yy = fmaf(BETA_F, yy - 10.0f,  10.0f); }
                if (yy < -10.0f) { lsum += LOG_BETA; yy = fmaf(BETA_F, yy + 10.0f, -10.0f); }
            }

            if (d < 4) prod0 *= DD; else prod1 *= DD;
            yv[d] = yy;
        }

        lsum = fmaf(__log2f(prod0) + __log2f(prod1), LN2_F, lsum) - EIGHT_LN20;

        stg256(y_out + (size_t)i * DIM, yv);    // one STG.E.256 per point
        ld_out[i] = ld_in + lsum;
    }
}

extern "C" void kernel_launch(void* const* d_in, const int* in_sizes, int n_in,
                              void* d_out, int out_size)
{
    const float* x      = (const float*)d_in[0];
    const float* logdet = (const float*)d_in[1];
    const float* p      = (const float*)d_in[2];
    float* out    = (float*)d_out;
    float* y_out  = out;                        // [N*8]
    float* ld_out = out + (size_t)NPTS * DIM;   // [N]

    cdf_fused_kernel<<<GRID, TPB>>>(x, logdet, p, y_out, ld_out);
}